// round 1
// baseline (speedup 1.0000x reference)
#include <cuda_runtime.h>
#include <math.h>

// ---------------------------------------------------------------------------
// SSIM (mean) for 64 x 1 x 512 x 512 fp32 image pairs, 11x11 Gaussian window.
//
// Key algebra:
//   ssim needs only conv(x), conv(y), conv(x^2+y^2), conv(x*y):
//     sigma1^2+sigma2^2 = conv(x^2+y^2) - mu1^2 - mu2^2
//     sigma12           = conv(x*y)     - mu1*mu2
//   window = outer(g,g)  ->  separable 11-tap passes, g recovered from row 5.
// ---------------------------------------------------------------------------

#define IMGW 512
#define IMGH 512
#define NIMG 64
#define TW 64                     // output tile width
#define TH 32                     // output tile height
#define RAD 5
#define IH (TH + 2*RAD)           // 42 input rows
#define IWD (TW + 2*RAD)          // 74 input cols
#define ISTR 75                   // smem stride for input-stage arrays (odd -> conflict free)
#define HSTR 65                   // smem stride for h-pass arrays (odd -> conflict free)
#define NTHREADS 256
#define TILES_X (IMGW / TW)       // 8
#define TILES_Y (IMGH / TH)       // 16
#define NBLOCKS (NIMG * TILES_X * TILES_Y)   // 8192

__device__ float g_partials[NBLOCKS];

// 11-tap symmetric conv on an 18-value register window -> 8 outputs.
__device__ __forceinline__ void conv8(const float v[18], float out[8],
                                      float w0, float w1, float w2,
                                      float w3, float w4, float w5) {
#pragma unroll
    for (int j = 0; j < 8; j++) {
        float acc = w5 * v[j + 5];
        acc = fmaf(w0, v[j + 0] + v[j + 10], acc);
        acc = fmaf(w1, v[j + 1] + v[j + 9], acc);
        acc = fmaf(w2, v[j + 2] + v[j + 8], acc);
        acc = fmaf(w3, v[j + 3] + v[j + 7], acc);
        acc = fmaf(w4, v[j + 4] + v[j + 6], acc);
        out[j] = acc;
    }
}

__global__ __launch_bounds__(NTHREADS)
void ssim_tile_kernel(const float* __restrict__ img1,
                      const float* __restrict__ img2,
                      const float* __restrict__ win) {
    extern __shared__ float smem[];
    float* sx = smem;                       // IH*ISTR
    float* sy = sx + IH * ISTR;
    float* sc = sy + IH * ISTR;             // x^2 + y^2
    float* se = sc + IH * ISTR;             // x * y
    float* ha = se + IH * ISTR;             // IH*HSTR  h-pass of x
    float* hb = ha + IH * HSTR;             // h-pass of y
    float* hc = hb + IH * HSTR;             // h-pass of x^2+y^2
    float* he = hc + IH * HSTR;             // h-pass of x*y
    float* gw = he + IH * HSTR;             // 11 (pad 12)
    float* red = gw + 12;                   // 8

    const int tid = threadIdx.x;

    // Recover separable 1-D Gaussian from the 2-D window (row 5 / sqrt(center)).
    if (tid < 11) {
        float g5 = sqrtf(win[5 * 11 + 5]);
        gw[tid] = win[5 * 11 + tid] / g5;
    }

    // ---- Stage inputs (zero-padded halo) + pointwise products -------------
    const int imgoff = blockIdx.z * (IMGW * IMGH);
    const float* p1 = img1 + imgoff;
    const float* p2 = img2 + imgoff;
    const int bx0 = blockIdx.x * TW - RAD;
    const int by0 = blockIdx.y * TH - RAD;

    for (int i = tid; i < IH * IWD; i += NTHREADS) {
        int r = i / IWD;
        int c = i - r * IWD;
        int gx = bx0 + c;
        int gy = by0 + r;
        float x = 0.f, y = 0.f;
        if ((unsigned)gx < (unsigned)IMGW && (unsigned)gy < (unsigned)IMGH) {
            int o = gy * IMGW + gx;
            x = __ldg(p1 + o);
            y = __ldg(p2 + o);
        }
        int si = r * ISTR + c;
        sx[si] = x;
        sy[si] = y;
        sc[si] = fmaf(x, x, y * y);
        se[si] = x * y;
    }
    __syncthreads();

    const float w0 = gw[0], w1 = gw[1], w2 = gw[2],
                w3 = gw[3], w4 = gw[4], w5 = gw[5];

    // ---- Horizontal pass: 8-wide strips, 18-value register windows -------
    // strips: consecutive tid -> consecutive rows (stride ISTR=75, conflict free)
    for (int s = tid; s < IH * (TW / 8); s += NTHREADS) {
        int r = s % IH;
        int cb = (s / IH) * 8;
        const int ib = r * ISTR + cb;
        const int ob = r * HSTR + cb;
        float v[18], o[8];

#pragma unroll
        for (int j = 0; j < 18; j++) v[j] = sx[ib + j];
        conv8(v, o, w0, w1, w2, w3, w4, w5);
#pragma unroll
        for (int j = 0; j < 8; j++) ha[ob + j] = o[j];

#pragma unroll
        for (int j = 0; j < 18; j++) v[j] = sy[ib + j];
        conv8(v, o, w0, w1, w2, w3, w4, w5);
#pragma unroll
        for (int j = 0; j < 8; j++) hb[ob + j] = o[j];

#pragma unroll
        for (int j = 0; j < 18; j++) v[j] = sc[ib + j];
        conv8(v, o, w0, w1, w2, w3, w4, w5);
#pragma unroll
        for (int j = 0; j < 8; j++) hc[ob + j] = o[j];

#pragma unroll
        for (int j = 0; j < 18; j++) v[j] = se[ib + j];
        conv8(v, o, w0, w1, w2, w3, w4, w5);
#pragma unroll
        for (int j = 0; j < 8; j++) he[ob + j] = o[j];
    }
    __syncthreads();

    // ---- Vertical pass: each thread owns an 8-tall column strip -----------
    const int c  = tid & (TW - 1);          // 0..63
    const int rb = (tid >> 6) * 8;          // row base 0,8,16,24
    float va[8], vb[8], vc[8], ve[8];
    {
        float v[18];
#pragma unroll
        for (int j = 0; j < 18; j++) v[j] = ha[(rb + j) * HSTR + c];
        conv8(v, va, w0, w1, w2, w3, w4, w5);
#pragma unroll
        for (int j = 0; j < 18; j++) v[j] = hb[(rb + j) * HSTR + c];
        conv8(v, vb, w0, w1, w2, w3, w4, w5);
#pragma unroll
        for (int j = 0; j < 18; j++) v[j] = hc[(rb + j) * HSTR + c];
        conv8(v, vc, w0, w1, w2, w3, w4, w5);
#pragma unroll
        for (int j = 0; j < 18; j++) v[j] = he[(rb + j) * HSTR + c];
        conv8(v, ve, w0, w1, w2, w3, w4, w5);
    }

    // ---- SSIM map + local accumulation ------------------------------------
    const float C1 = 0.0001f;   // 0.01^2
    const float C2 = 0.0009f;   // 0.03^2
    float sum = 0.f;
#pragma unroll
    for (int j = 0; j < 8; j++) {
        float mu1 = va[j], mu2 = vb[j];
        float m11 = mu1 * mu1;
        float m22 = mu2 * mu2;
        float m12 = mu1 * mu2;
        float s12  = ve[j] - m12;
        float ssum = vc[j] - m11 - m22;
        float num = fmaf(2.f, m12, C1) * fmaf(2.f, s12, C2);
        float den = (m11 + m22 + C1) * (ssum + C2);
        sum += __fdividef(num, den);
    }

    // ---- Deterministic block reduction ------------------------------------
#pragma unroll
    for (int o = 16; o; o >>= 1)
        sum += __shfl_down_sync(0xffffffffu, sum, o);
    if ((tid & 31) == 0) red[tid >> 5] = sum;
    __syncthreads();
    if (tid == 0) {
        float t = 0.f;
#pragma unroll
        for (int w = 0; w < NTHREADS / 32; w++) t += red[w];
        int bi = (blockIdx.z * gridDim.y + blockIdx.y) * gridDim.x + blockIdx.x;
        g_partials[bi] = t;
    }
}

__global__ void ssim_reduce_kernel(float* __restrict__ out) {
    __shared__ float sm[256];
    float s = 0.f;
    for (int i = threadIdx.x; i < NBLOCKS; i += 256) s += g_partials[i];
    sm[threadIdx.x] = s;
    __syncthreads();
#pragma unroll
    for (int o = 128; o; o >>= 1) {
        if (threadIdx.x < o) sm[threadIdx.x] += sm[threadIdx.x + o];
        __syncthreads();
    }
    if (threadIdx.x == 0)
        out[0] = sm[0] * (1.0f / (float)((long long)NIMG * IMGW * IMGH));
}

extern "C" void kernel_launch(void* const* d_in, const int* in_sizes, int n_in,
                              void* d_out, int out_size) {
    const float* img1 = (const float*)d_in[0];
    const float* img2 = (const float*)d_in[1];
    const float* win  = (const float*)d_in[2];

    const size_t SMEM = (size_t)(4 * IH * ISTR + 4 * IH * HSTR + 12 + 8) * sizeof(float);
    cudaFuncSetAttribute(ssim_tile_kernel,
                         cudaFuncAttributeMaxDynamicSharedMemorySize, (int)SMEM);

    dim3 grid(TILES_X, TILES_Y, NIMG);
    ssim_tile_kernel<<<grid, NTHREADS, SMEM>>>(img1, img2, win);
    ssim_reduce_kernel<<<1, 256>>>((float*)d_out);
}